// round 17
// baseline (speedup 1.0000x reference)
#include <cuda_runtime.h>
#include <stdint.h>

// TrafficGCN: 2-layer GCN, N=100000, E=3200000, HIDDEN=16.
// R17: single persistent kernel. Phases (zero -> CSR build -> node1 ->
// pull1(+MLP) -> pull2(+out)) separated by a software grid barrier.
// Grid = occupancy-guaranteed co-resident blocks. Cross-phase data read
// with __ldcg (L2) -- __ldg (.nc) is ILLEGAL on same-kernel-written data.
// Pull structure = R8 best: 8 lanes/node, dual int4 index prefetch, MLP<=8.
//
// Inputs: d_in[0]=x f32[N,3], d_in[1]=edge_index i32[2,E],
//         d_in[2]=W1 f32[3,16], d_in[3]=b1 f32[16], d_in[4]=W2 f32[16,1],
//         d_in[5]=b2 f32[1].  Output: f32[N].

#define MAXN 100608
#define HID 16
#define CAP 64
#define OVF_CAP 65536

__device__ int    g_cnt[MAXN];
__device__ int    g_csr[(size_t)MAXN * CAP];
__device__ int    g_ovf_cnt;
__device__ int2   g_ovf[OVF_CAP];
__device__ float  g_isd[MAXN];
__device__ float4 g_px[MAXN];
__device__ float  g_p[MAXN];

__device__ unsigned g_bar_count = 0;
__device__ unsigned g_bar_gen   = 0;

// Generation-counter grid barrier. Every thread of every block must call.
__device__ __forceinline__ void grid_barrier(int nblocks) {
    __syncthreads();
    if (threadIdx.x == 0) {
        unsigned gen = *(volatile unsigned*)&g_bar_gen;
        __threadfence();                       // publish this block's writes
        unsigned t = atomicAdd(&g_bar_count, 1u);
        if (t == (unsigned)nblocks - 1u) {
            g_bar_count = 0;                   // reset BEFORE release
            __threadfence();
            atomicAdd(&g_bar_gen, 1u);         // release
        } else {
            while (*(volatile unsigned*)&g_bar_gen == gen) { }
        }
        __threadfence();
    }
    __syncthreads();
}

__device__ __forceinline__ void build_one(int s, int d) {
    int slot = atomicAdd(&g_cnt[d], 1);
    if (slot < CAP) {
        g_csr[(size_t)d * CAP + slot] = s;
    } else {
        int o = atomicAdd(&g_ovf_cnt, 1);
        if (o < OVF_CAP) g_ovf[o] = make_int2(s, d);
    }
}

extern "C" __global__ void __launch_bounds__(256, 6)
gcn_fused(const float* __restrict__ x,
          const int*   __restrict__ src,
          const int*   __restrict__ dst,
          const float* __restrict__ W1,
          const float* __restrict__ b1,
          const float* __restrict__ W2,
          const float* __restrict__ b2,
          float* __restrict__ out,
          int n, int E, int nblocks) {
    const int tid      = blockIdx.x * blockDim.x + threadIdx.x;
    const int nthreads = gridDim.x * blockDim.x;
    const int lane     = threadIdx.x & 31;

    // ---- Phase 0: zero counters -----------------------------------------
    for (int i = tid; i < n; i += nthreads) g_cnt[i] = 0;
    if (tid == 0) g_ovf_cnt = 0;
    grid_barrier(nblocks);

    // ---- Phase 1: CSR build (8 edges/thread, int4 index loads) ----------
    {
        int E8 = E >> 3;
        for (int t = tid; t < E8; t += nthreads) {
            int4 s0 = ((const int4*)src)[2 * t];
            int4 s1 = ((const int4*)src)[2 * t + 1];
            int4 d0 = ((const int4*)dst)[2 * t];
            int4 d1 = ((const int4*)dst)[2 * t + 1];
            build_one(s0.x, d0.x); build_one(s0.y, d0.y);
            build_one(s0.z, d0.z); build_one(s0.w, d0.w);
            build_one(s1.x, d1.x); build_one(s1.y, d1.y);
            build_one(s1.z, d1.z); build_one(s1.w, d1.w);
        }
        for (int e = (E8 << 3) + tid; e < E; e += nthreads)
            build_one(src[e], dst[e]);
    }
    grid_barrier(nblocks);

    // ---- Phase 2: isd + px ----------------------------------------------
    for (int i = tid; i < n; i += nthreads) {
        float isd = rsqrtf((float)(__ldcg(&g_cnt[i]) + 1));
        g_isd[i] = isd;
        g_px[i] = make_float4(isd * x[3*i+0], isd * x[3*i+1], isd * x[3*i+2], 0.f);
    }
    grid_barrier(nblocks);

    // ---- Phase 3: layer-1 pull + fused MLP (8 lanes/node, 4 nodes/warp) --
    {
        const int warp = tid >> 5, nw = nthreads >> 5;
        const int j    = lane & 7;
        const int grp  = lane >> 3;
        const unsigned gmask = 0xFFu << (grp * 8);

        const int c0 = j, c1 = j + 8;
        const float w00 = __ldg(&W1[c0]),         w01 = __ldg(&W1[c1]);
        const float w10 = __ldg(&W1[HID + c0]),   w11 = __ldg(&W1[HID + c1]);
        const float w20 = __ldg(&W1[2*HID + c0]), w21 = __ldg(&W1[2*HID + c1]);
        const float bb0 = __ldg(&b1[c0]),         bb1 = __ldg(&b1[c1]);
        const float v20 = __ldg(&W2[c0]),         v21 = __ldg(&W2[c1]);

        const int ngrp4 = (n + 3) >> 2;
        for (int q = warp; q < ngrp4; q += nw) {
            int d = q * 4 + grp;
            bool valid = d < n;
            int dc = valid ? d : 0;
            int m = valid ? min(__ldcg(&g_cnt[dc]), CAP) : 0;
            const int4* row4 = (const int4*)(g_csr + (size_t)dc * CAP);

            int sA = 4 * j, sB = 32 + 4 * j;
            int4 iA, iB;
            if (sA < m) iA = __ldcg(&row4[j]);
            if (sB < m) iB = __ldcg(&row4[j + 8]);

            float ax = 0.f, ay = 0.f, az = 0.f;
            if (valid && j == 0) {
                float4 sv = __ldcg(&g_px[dc]);
                ax = sv.x; ay = sv.y; az = sv.z;
            }
            if (sA < m) {
                { float4 v = __ldcg(&g_px[iA.x]); ax += v.x; ay += v.y; az += v.z; }
                if (sA + 1 < m) { float4 v = __ldcg(&g_px[iA.y]); ax += v.x; ay += v.y; az += v.z; }
                if (sA + 2 < m) { float4 v = __ldcg(&g_px[iA.z]); ax += v.x; ay += v.y; az += v.z; }
                if (sA + 3 < m) { float4 v = __ldcg(&g_px[iA.w]); ax += v.x; ay += v.y; az += v.z; }
            }
            if (sB < m) {
                { float4 v = __ldcg(&g_px[iB.x]); ax += v.x; ay += v.y; az += v.z; }
                if (sB + 1 < m) { float4 v = __ldcg(&g_px[iB.y]); ax += v.x; ay += v.y; az += v.z; }
                if (sB + 2 < m) { float4 v = __ldcg(&g_px[iB.z]); ax += v.x; ay += v.y; az += v.z; }
                if (sB + 3 < m) { float4 v = __ldcg(&g_px[iB.w]); ax += v.x; ay += v.y; az += v.z; }
            }
            int ovn = __ldcg(&g_ovf_cnt);
            if (ovn > 0) {
                for (int t = j; t < ovn; t += 8) {
                    int2 e = g_ovf[t];
                    if (valid && e.y == d) {
                        float4 v = __ldcg(&g_px[e.x]);
                        ax += v.x; ay += v.y; az += v.z;
                    }
                }
            }
#pragma unroll
            for (int o = 4; o; o >>= 1) {
                ax += __shfl_xor_sync(gmask, ax, o);
                ay += __shfl_xor_sync(gmask, ay, o);
                az += __shfl_xor_sync(gmask, az, o);
            }
            float isd = __ldcg(&g_isd[dc]);
            float f0 = isd * ax, f1 = isd * ay, f2 = isd * az;
            float h0 = fmaxf(f0 * w00 + f1 * w10 + f2 * w20 + bb0, 0.f);
            float h1 = fmaxf(f0 * w01 + f1 * w11 + f2 * w21 + bb1, 0.f);
            float ps = h0 * v20 + h1 * v21;
#pragma unroll
            for (int o = 4; o; o >>= 1) ps += __shfl_xor_sync(gmask, ps, o);
            if (valid && j == 0) g_p[d] = isd * ps;
        }
    }
    grid_barrier(nblocks);

    // ---- Phase 4: layer-2 pull + final output ----------------------------
    {
        const int warp = tid >> 5, nw = nthreads >> 5;
        const int j    = lane & 7;
        const int grp  = lane >> 3;
        const unsigned gmask = 0xFFu << (grp * 8);
        const float bias2 = __ldg(&b2[0]);

        const int ngrp4 = (n + 3) >> 2;
        for (int q = warp; q < ngrp4; q += nw) {
            int d = q * 4 + grp;
            bool valid = d < n;
            int dc = valid ? d : 0;
            int m = valid ? min(__ldcg(&g_cnt[dc]), CAP) : 0;
            const int4* row4 = (const int4*)(g_csr + (size_t)dc * CAP);

            int sA = 4 * j, sB = 32 + 4 * j;
            int4 iA, iB;
            if (sA < m) iA = __ldcg(&row4[j]);
            if (sB < m) iB = __ldcg(&row4[j + 8]);

            float a = (valid && j == 0) ? __ldcg(&g_p[dc]) : 0.f;  // self-loop
            if (sA < m) {
                a += __ldcg(&g_p[iA.x]);
                if (sA + 1 < m) a += __ldcg(&g_p[iA.y]);
                if (sA + 2 < m) a += __ldcg(&g_p[iA.z]);
                if (sA + 3 < m) a += __ldcg(&g_p[iA.w]);
            }
            if (sB < m) {
                a += __ldcg(&g_p[iB.x]);
                if (sB + 1 < m) a += __ldcg(&g_p[iB.y]);
                if (sB + 2 < m) a += __ldcg(&g_p[iB.z]);
                if (sB + 3 < m) a += __ldcg(&g_p[iB.w]);
            }
            int ovn = __ldcg(&g_ovf_cnt);
            if (ovn > 0) {
                for (int t = j; t < ovn; t += 8) {
                    int2 e = g_ovf[t];
                    if (valid && e.y == d) a += __ldcg(&g_p[e.x]);
                }
            }
#pragma unroll
            for (int o = 4; o; o >>= 1) a += __shfl_xor_sync(gmask, a, o);
            if (valid && j == 0)
                out[d] = bias2 + __ldcg(&g_isd[dc]) * a;
        }
    }
}

// ---------------------------------------------------------------------------
extern "C" void kernel_launch(void* const* d_in, const int* in_sizes, int n_in,
                              void* d_out, int out_size) {
    const float* x  = (const float*)d_in[0];
    const int*   ei = (const int*)  d_in[1];
    const float* W1 = (const float*)d_in[2];
    const float* b1 = (const float*)d_in[3];
    const float* W2 = (const float*)d_in[4];
    const float* b2 = (const float*)d_in[5];
    float* out = (float*)d_out;

    int n = in_sizes[0] / 3;
    int E = in_sizes[1] / 2;
    const int* src = ei;
    const int* dst = ei + E;

    const int T = 256;
    int blocksPerSM = 0, numSM = 0;
    cudaOccupancyMaxActiveBlocksPerMultiprocessor(&blocksPerSM, gcn_fused, T, 0);
    cudaDeviceGetAttribute(&numSM, cudaDevAttrMultiProcessorCount, 0);
    if (blocksPerSM < 1) blocksPerSM = 1;
    int nblocks = blocksPerSM * numSM;

    gcn_fused<<<nblocks, T>>>(x, src, dst, W1, b1, W2, b2, out, n, E, nblocks);
}